// round 1
// baseline (speedup 1.0000x reference)
#include <cuda_runtime.h>

#define N_NODES 50000
#define DIM 128
#define N_EDGES 800000
#define N_OUT 47

// Scratch (device globals — no allocations allowed)
__device__ float g_hA[N_NODES * DIM];
__device__ float g_hB[N_NODES * DIM];
__device__ float g_mean[N_NODES * DIM];
__device__ int   g_rowptr[N_NODES + 1];
__device__ int   g_cursor[N_NODES];
__device__ int   g_esrc[N_EDGES];
__device__ float g_wT[2 * DIM * DIM];   // [256][128] transposed concat weights

// ---------------- CSR build (by dst) ----------------

__global__ void zero_cursor_k() {
    int i = blockIdx.x * blockDim.x + threadIdx.x;
    if (i < N_NODES) g_cursor[i] = 0;
}

__global__ void count_k(const int* __restrict__ dst) {
    int e = blockIdx.x * blockDim.x + threadIdx.x;
    if (e < N_EDGES) atomicAdd(&g_cursor[dst[e]], 1);
}

// Single-block exclusive scan over 50000 counts -> rowptr, and reset cursor=rowptr
__global__ void scan_k() {
    __shared__ int ssum[1024];
    int t = threadIdx.x;
    const int CH = (N_NODES + 1023) / 1024;  // 49
    int base = t * CH;
    int s = 0;
    for (int i = 0; i < CH; i++) {
        int idx = base + i;
        if (idx < N_NODES) s += g_cursor[idx];
    }
    ssum[t] = s;
    __syncthreads();
    for (int off = 1; off < 1024; off <<= 1) {
        int v = 0;
        if (t >= off) v = ssum[t - off];
        __syncthreads();
        if (t >= off) ssum[t] += v;
        __syncthreads();
    }
    int run = (t == 0) ? 0 : ssum[t - 1];
    for (int i = 0; i < CH; i++) {
        int idx = base + i;
        if (idx < N_NODES) {
            int c = g_cursor[idx];
            g_rowptr[idx] = run;
            g_cursor[idx] = run;
            run += c;
        }
    }
    if (t == 0) g_rowptr[N_NODES] = N_EDGES;
}

__global__ void bucket_k(const int* __restrict__ src, const int* __restrict__ dst) {
    int e = blockIdx.x * blockDim.x + threadIdx.x;
    if (e < N_EDGES) {
        int pos = atomicAdd(&g_cursor[dst[e]], 1);
        g_esrc[pos] = src[e];
    }
}

// ---------------- weight transpose: g_wT[k][c] = (k<128 ? ws[c][k] : wn[c][k-128]) ----------------

__global__ void wT_k(const float* __restrict__ ws, const float* __restrict__ wn, int nout) {
    int idx = blockIdx.x * blockDim.x + threadIdx.x;
    if (idx >= 2 * DIM * DIM) return;
    int k = idx / DIM, c = idx % DIM;
    float v = 0.f;
    if (c < nout) v = (k < DIM) ? ws[c * DIM + k] : wn[c * DIM + (k - DIM)];
    g_wT[idx] = v;
}

// ---------------- mean aggregation: one warp per node ----------------

__global__ void agg_k(const float* __restrict__ h) {
    int gt = blockIdx.x * blockDim.x + threadIdx.x;
    int node = gt >> 5, lane = gt & 31;
    if (node >= N_NODES) return;
    int beg = g_rowptr[node], end = g_rowptr[node + 1];
    float4 acc = make_float4(0.f, 0.f, 0.f, 0.f);
    for (int j = beg; j < end; j++) {
        int s = g_esrc[j];
        float4 v = ((const float4*)(h + (size_t)s * DIM))[lane];
        acc.x += v.x; acc.y += v.y; acc.z += v.z; acc.w += v.w;
    }
    float inv = 1.f / fmaxf((float)(end - beg), 1.f);
    acc.x *= inv; acc.y *= inv; acc.z *= inv; acc.w *= inv;
    ((float4*)(g_mean + (size_t)node * DIM))[lane] = acc;
}

// ---------------- fused SAGE GEMM: out = [h | mean] @ g_wT + b, optional ReLU ----------------
// A = concat(h[N,128], mean[N,128]) -> K=256.  BM=128, BN=128, BK=16, 256 thr, 8x8 per thread.

template <int NOUT, bool RELU>
__global__ void gemm_k(const float* __restrict__ A0, const float* __restrict__ bias,
                       float* __restrict__ out) {
    __shared__ float As[16][128];
    __shared__ float Bs[16][128];
    int tid = threadIdx.x;
    int tx = tid % 16, ty = tid / 16;
    int rowBase = blockIdx.x * 128;

    float acc[8][8];
#pragma unroll
    for (int i = 0; i < 8; i++)
#pragma unroll
        for (int j = 0; j < 8; j++) acc[i][j] = 0.f;

    int la_c = tid % 4;  // which float4 along k
    int la_r = tid / 4;  // row 0..63 (+64)

    for (int k0 = 0; k0 < 256; k0 += 16) {
        // A tile (transposed into As[k][m]); mean scaled rows come from g_mean
#pragma unroll
        for (int p = 0; p < 2; p++) {
            int r = la_r + p * 64;
            int gr = rowBase + r;
            int gk = k0 + la_c * 4;
            float4 v = make_float4(0.f, 0.f, 0.f, 0.f);
            if (gr < N_NODES) {
                if (gk < 128) v = *(const float4*)(A0 + (size_t)gr * 128 + gk);
                else          v = *(const float4*)(g_mean + (size_t)gr * 128 + (gk - 128));
            }
            As[la_c * 4 + 0][r] = v.x;
            As[la_c * 4 + 1][r] = v.y;
            As[la_c * 4 + 2][r] = v.z;
            As[la_c * 4 + 3][r] = v.w;
        }
        // B tile
#pragma unroll
        for (int p = 0; p < 8; p++) {
            int idx = tid + p * 256;
            int k = idx / 128, n = idx % 128;
            Bs[k][n] = g_wT[(k0 + k) * 128 + n];
        }
        __syncthreads();

#pragma unroll
        for (int k = 0; k < 16; k++) {
            float a[8], b[8];
            *(float4*)&a[0] = *(const float4*)&As[k][ty * 8];
            *(float4*)&a[4] = *(const float4*)&As[k][ty * 8 + 4];
            *(float4*)&b[0] = *(const float4*)&Bs[k][tx * 8];
            *(float4*)&b[4] = *(const float4*)&Bs[k][tx * 8 + 4];
#pragma unroll
            for (int i = 0; i < 8; i++)
#pragma unroll
                for (int j = 0; j < 8; j++)
                    acc[i][j] += a[i] * b[j];
        }
        __syncthreads();
    }

#pragma unroll
    for (int i = 0; i < 8; i++) {
        int gr = rowBase + ty * 8 + i;
        if (gr >= N_NODES) continue;
#pragma unroll
        for (int j = 0; j < 8; j++) {
            int gc = tx * 8 + j;
            if (gc < NOUT) {
                float v = acc[i][j] + bias[gc];
                if (RELU) v = fmaxf(v, 0.f);
                out[(size_t)gr * NOUT + gc] = v;
            }
        }
    }
}

// ---------------- launch ----------------

extern "C" void kernel_launch(void* const* d_in, const int* in_sizes, int n_in,
                              void* d_out, int out_size) {
    const float* x   = (const float*)d_in[0];
    const int*   src = (const int*)d_in[1];
    const int*   dst = (const int*)d_in[2];
    const float* ws1 = (const float*)d_in[3];
    const float* wn1 = (const float*)d_in[4];
    const float* b1  = (const float*)d_in[5];
    const float* ws2 = (const float*)d_in[6];
    const float* wn2 = (const float*)d_in[7];
    const float* b2  = (const float*)d_in[8];
    const float* ws3 = (const float*)d_in[9];
    const float* wn3 = (const float*)d_in[10];
    const float* b3  = (const float*)d_in[11];
    float* out = (float*)d_out;

    void *pA = nullptr, *pB = nullptr;
    cudaGetSymbolAddress(&pA, g_hA);
    cudaGetSymbolAddress(&pB, g_hB);
    float* hA = (float*)pA;
    float* hB = (float*)pB;

    const int EB = (N_EDGES + 255) / 256;
    const int NB = (N_NODES + 255) / 256;
    const int WB = (2 * DIM * DIM + 255) / 256;
    const int AGG_B = (N_NODES * 32 + 255) / 256;
    const int GEMM_B = (N_NODES + 127) / 128;

    // CSR build (per call; deterministic work)
    zero_cursor_k<<<NB, 256>>>();
    count_k<<<EB, 256>>>(dst);
    scan_k<<<1, 1024>>>();
    bucket_k<<<EB, 256>>>(src, dst);

    // Layer 1
    wT_k<<<WB, 256>>>(ws1, wn1, DIM);
    agg_k<<<AGG_B, 256>>>(x);
    gemm_k<128, true><<<GEMM_B, 256>>>(x, b1, hA);

    // Layer 2
    wT_k<<<WB, 256>>>(ws2, wn2, DIM);
    agg_k<<<AGG_B, 256>>>(hA);
    gemm_k<128, true><<<GEMM_B, 256>>>(hA, b2, hB);

    // Layer 3
    wT_k<<<WB, 256>>>(ws3, wn3, N_OUT);
    agg_k<<<AGG_B, 256>>>(hB);
    gemm_k<N_OUT, false><<<GEMM_B, 256>>>(hB, b3, out);
}

// round 8
// speedup vs baseline: 1.5009x; 1.5009x over previous
#include <cuda_runtime.h>
#include <cuda_bf16.h>
#include <cstdint>

#define N_NODES 50000
#define DIM 128
#define N_EDGES 800000
#define N_OUT 47

// ---------------- scratch (device globals; no allocation allowed) ----------------
__device__ float g_hA[N_NODES * DIM];
__device__ float g_hB[N_NODES * DIM];
__device__ float g_mean[N_NODES * DIM];
__device__ int   g_rowptr[N_NODES + 1];
__device__ int   g_cursor[N_NODES];
__device__ int   g_esrc[N_EDGES];
__device__ __align__(16) __nv_bfloat16 g_Bhi[128 * 256];  // B hi, row-major [N][256]
__device__ __align__(16) __nv_bfloat16 g_Blo[128 * 256];  // B lo

// ---------------- CSR build (by dst) ----------------

__global__ void zero_cursor_k() {
    int i = blockIdx.x * blockDim.x + threadIdx.x;
    if (i < N_NODES) g_cursor[i] = 0;
}
__global__ void count_k(const int* __restrict__ dst) {
    int e = blockIdx.x * blockDim.x + threadIdx.x;
    if (e < N_EDGES) atomicAdd(&g_cursor[dst[e]], 1);
}
__global__ void scan_k() {
    __shared__ int ssum[1024];
    int t = threadIdx.x;
    const int CH = (N_NODES + 1023) / 1024;
    int base = t * CH;
    int s = 0;
    for (int i = 0; i < CH; i++) { int idx = base + i; if (idx < N_NODES) s += g_cursor[idx]; }
    ssum[t] = s;
    __syncthreads();
    for (int off = 1; off < 1024; off <<= 1) {
        int v = 0;
        if (t >= off) v = ssum[t - off];
        __syncthreads();
        if (t >= off) ssum[t] += v;
        __syncthreads();
    }
    int run = (t == 0) ? 0 : ssum[t - 1];
    for (int i = 0; i < CH; i++) {
        int idx = base + i;
        if (idx < N_NODES) {
            int c = g_cursor[idx];
            g_rowptr[idx] = run;
            g_cursor[idx] = run;
            run += c;
        }
    }
    if (t == 0) g_rowptr[N_NODES] = N_EDGES;
}
__global__ void bucket_k(const int* __restrict__ src, const int* __restrict__ dst) {
    int e = blockIdx.x * blockDim.x + threadIdx.x;
    if (e < N_EDGES) {
        int pos = atomicAdd(&g_cursor[dst[e]], 1);
        g_esrc[pos] = src[e];
    }
}

// ---------------- mean aggregation: one warp per node, 2-edge unroll for MLP ----------------

__global__ void agg_k(const float* __restrict__ h) {
    int gt = blockIdx.x * blockDim.x + threadIdx.x;
    int node = gt >> 5, lane = gt & 31;
    if (node >= N_NODES) return;
    int beg = g_rowptr[node], end = g_rowptr[node + 1];
    float4 acc0 = make_float4(0.f, 0.f, 0.f, 0.f);
    float4 acc1 = make_float4(0.f, 0.f, 0.f, 0.f);
    int j = beg;
    for (; j + 1 < end; j += 2) {
        int s0 = g_esrc[j], s1 = g_esrc[j + 1];
        float4 v0 = ((const float4*)(h + (size_t)s0 * DIM))[lane];
        float4 v1 = ((const float4*)(h + (size_t)s1 * DIM))[lane];
        acc0.x += v0.x; acc0.y += v0.y; acc0.z += v0.z; acc0.w += v0.w;
        acc1.x += v1.x; acc1.y += v1.y; acc1.z += v1.z; acc1.w += v1.w;
    }
    if (j < end) {
        int s0 = g_esrc[j];
        float4 v0 = ((const float4*)(h + (size_t)s0 * DIM))[lane];
        acc0.x += v0.x; acc0.y += v0.y; acc0.z += v0.z; acc0.w += v0.w;
    }
    float inv = 1.f / fmaxf((float)(end - beg), 1.f);
    acc0.x = (acc0.x + acc1.x) * inv;
    acc0.y = (acc0.y + acc1.y) * inv;
    acc0.z = (acc0.z + acc1.z) * inv;
    acc0.w = (acc0.w + acc1.w) * inv;
    ((float4*)(g_mean + (size_t)node * DIM))[lane] = acc0;
}

// ---------------- B prep: W[n][k] -> hi/lo bf16 row-major [NT][256] (k<128: w_self, else w_neigh) ----------------

__global__ void prepB_k(const float* __restrict__ ws, const float* __restrict__ wn,
                        int nout, int NT) {
    int idx = blockIdx.x * blockDim.x + threadIdx.x;
    if (idx >= NT * 256) return;
    int n = idx / 256, k = idx % 256;
    float v = 0.f;
    if (n < nout) v = (k < 128) ? ws[n * 128 + k] : wn[n * 128 + (k - 128)];
    __nv_bfloat16 h = __float2bfloat16(v);
    __nv_bfloat16 l = __float2bfloat16(v - __bfloat162float(h));
    g_Bhi[idx] = h;
    g_Blo[idx] = l;
}

// ---------------- mma.sync split-bf16 GEMM: out = relu?([h|mean] @ W^T + b) ----------------
// 256 thr = 8 warps (4m x 2n). CTA tile 128 x BN, BK=32. m16n8k16 bf16 HMMA, fp32 accum.
// 3 products per k-step: Ahi*Bhi + Ahi*Blo + Alo*Bhi.

__device__ __forceinline__ void mma16816(float* c, const uint32_t* a, const uint32_t* b) {
    asm volatile(
        "mma.sync.aligned.m16n8k16.row.col.f32.bf16.bf16.f32 "
        "{%0,%1,%2,%3}, {%4,%5,%6,%7}, {%8,%9}, {%0,%1,%2,%3};"
        : "+f"(c[0]), "+f"(c[1]), "+f"(c[2]), "+f"(c[3])
        : "r"(a[0]), "r"(a[1]), "r"(a[2]), "r"(a[3]), "r"(b[0]), "r"(b[1]));
}

__device__ __forceinline__ uint32_t pack_bf16(__nv_bfloat16 l, __nv_bfloat16 h) {
    return ((uint32_t)__bfloat16_as_ushort(h) << 16) | __bfloat16_as_ushort(l);
}

#define BKP 40  // padded row: 32 bf16 + 8 (row stride 80B = 20 words -> conflict-free frags)

template <int BN, int NOUT, bool RELU>
__global__ void __launch_bounds__(256) gemm_mma(const float* __restrict__ A0,
                                                const float* __restrict__ bias,
                                                float* __restrict__ out) {
    constexpr int HN = BN / 2;    // warp n-extent
    constexpr int NF = HN / 8;    // n-frags per warp
    __shared__ __align__(16) uint16_t As_hi[128][BKP];
    __shared__ __align__(16) uint16_t As_lo[128][BKP];
    __shared__ __align__(16) uint16_t Bs_hi[BN][BKP];
    __shared__ __align__(16) uint16_t Bs_lo[BN][BKP];

    int tid = threadIdx.x;
    int warp = tid >> 5, lane = tid & 31;
    int wm = warp & 3, wn = warp >> 2;
    int qrow = lane >> 2, qk2 = (lane & 3) * 2;
    int rowBase = blockIdx.x * 128;

    float c[2][NF][4];
#pragma unroll
    for (int mi = 0; mi < 2; mi++)
#pragma unroll
        for (int ni = 0; ni < NF; ni++)
#pragma unroll
            for (int j = 0; j < 4; j++) c[mi][ni][j] = 0.f;

    const uint32_t* Bhi_u = (const uint32_t*)g_Bhi;
    const uint32_t* Blo_u = (const uint32_t*)g_Blo;

    for (int kb = 0; kb < 256; kb += 32) {
        // ---- stage A: 128 rows x 32 fp32 -> hi/lo bf16 smem ----
        const float* srcA = (kb < 128) ? (A0 + kb) : (g_mean + (kb - 128));
#pragma unroll
        for (int i = 0; i < 4; i++) {
            int idx = tid + i * 256;           // 0..1023 float4s
            int r = idx >> 3, q = idx & 7;
            int gr = rowBase + r;
            if (gr >= N_NODES) gr = N_NODES - 1;  // clamp; extra rows never stored
            float4 v = *(const float4*)(srcA + (size_t)gr * 128 + q * 4);
            __nv_bfloat16 h0 = __float2bfloat16(v.x), h1 = __float2bfloat16(v.y);
            __nv_bfloat16 h2 = __float2bfloat16(v.z), h3 = __float2bfloat16(v.w);
            __nv_bfloat16 l0 = __float2bfloat16(v.x - __bfloat162float(h0));
            __nv_bfloat16 l1 = __float2bfloat16(v.y - __bfloat162float(h1));
            __nv_bfloat16 l2 = __float2bfloat16(v.z - __bfloat162float(h2));
            __nv_bfloat16 l3 = __float2bfloat16(v.w - __bfloat162float(h3));
            *(uint32_t*)&As_hi[r][q * 4 + 0] = pack_bf16(h0, h1);
            *(uint32_t*)&As_hi[r][q * 4 + 2] = pack_bf16(h2, h3);
            *(uint32_t*)&As_lo[r][q * 4 + 0] = pack_bf16(l0, l1);
            *(uint32_t*)&As_lo[r][q * 4 + 2] = pack_bf16(l2, l3);
        }
        // ---- stage B: BN rows x 32 bf16 (hi & lo) ----
#pragma unroll
        for (int i = 0; i < BN / 16; i++) {
            int idx = tid + i * 256;           // BN*16 uints
            int n = idx >> 4, u = idx & 15;
            uint32_t vh = __ldg(Bhi_u + n * 128 + kb / 2 + u);
            uint32_t vl = __ldg(Blo_u + n * 128 + kb / 2 + u);
            *(uint32_t*)&Bs_hi[n][u * 2] = vh;
            *(uint32_t*)&Bs_lo[n][u * 2] = vl;
        }
        __syncthreads();

        // ---- compute: 2 k16 steps ----
#pragma unroll
        for (int kk = 0; kk < 2; kk++) {
            int k0 = kk * 16;
            uint32_t a_hi[2][4], a_lo[2][4];
#pragma unroll
            for (int mi = 0; mi < 2; mi++) {
                int r = wm * 32 + mi * 16 + qrow;
                a_hi[mi][0] = *(const uint32_t*)&As_hi[r][k0 + qk2];
                a_hi[mi][1] = *(const uint32_t*)&As_hi[r + 8][k0 + qk2];
                a_hi[mi][2] = *(const uint32_t*)&As_hi[r][k0 + qk2 + 8];
                a_hi[mi][3] = *(const uint32_t*)&As_hi[r + 8][k0 + qk2 + 8];
                a_lo[mi][0] = *(const uint32_t*)&As_lo[r][k0 + qk2];
                a_lo[mi][1] = *(const uint32_t*)&As_lo[r + 8][k0 + qk2];
                a_lo[mi][2] = *(const uint32_t*)&As_lo[r][k0 + qk2 + 8];
                a_lo[mi][3] = *(const uint32_t*)&As_lo[r + 8][k0 + qk2 + 8];
            }
            uint32_t b_hi[NF][2], b_lo[NF][2];
#pragma unroll
            for (int ni = 0; ni < NF; ni++) {
                int n = wn * HN + ni * 8 + qrow;
                b_hi[ni][0] = *(const uint32_t*)&Bs_hi[n][k0 + qk2];
                b_hi[ni][1] = *(const uint32_t*)&Bs_hi[n][k0 + qk2 + 8];
                b_lo[ni][0] = *(const uint32_t*)&Bs_lo[n][k0 + qk2];
                b_lo[ni][1] = *(const uint32_t*)&Bs_lo[n][k0 + qk2 + 8];
            }
#pragma unroll
            for (int mi = 0; mi < 2; mi++)
#pragma unroll
                for (int ni = 0; ni < NF; ni++) {
                    mma16816(c[mi][ni], a_hi[mi], b_hi[ni]);
                    mma16816(c[mi][ni], a_hi[mi], b_lo[ni]);
                    mma16816(c[mi][ni], a_lo[mi], b_hi[ni]);
                }
        }
        __syncthreads();
    }

    // ---- epilogue: bias + optional ReLU, guarded scatter ----
#pragma unroll
    for (int mi = 0; mi < 2; mi++) {
        int r0 = rowBase + wm * 32 + mi * 16 + qrow;
#pragma unroll
        for (int ni = 0; ni < NF; ni++) {
            int col = wn * HN + ni * 8 + qk2;
            float b0 = (col < NOUT) ? bias[col] : 0.f;
            float b1 = (col + 1 < NOUT) ? bias[col + 1] : 0.f;
            float v0 = c[mi][ni][0] + b0, v1 = c[mi][ni][1] + b1;
            float v2 = c[mi][ni][2] + b0, v3 = c[mi][ni][3] + b1;
            if (RELU) {
                v0 = fmaxf(v0, 0.f); v1 = fmaxf(v1, 0.f);
                v2 = fmaxf(v2, 0.f); v3 = fmaxf(v3, 0.f);
            }
            if (r0 < N_NODES) {
                if (col < NOUT)     out[(size_t)r0 * NOUT + col]     = v0;
                if (col + 1 < NOUT) out[(size_t)r0 * NOUT + col + 1] = v1;
            }
            if (r0 + 8 < N_NODES) {
                if (col < NOUT)     out[(size_t)(r0 + 8) * NOUT + col]     = v2;
                if (col + 1 < NOUT) out[(size_t)(r0 + 8) * NOUT + col + 1] = v3;
            }
        }
    }
}

// ---------------- launch ----------------

extern "C" void kernel_launch(void* const* d_in, const int* in_sizes, int n_in,
                              void* d_out, int out_size) {
    const float* x   = (const float*)d_in[0];
    const int*   src = (const int*)d_in[1];
    const int*   dst = (const int*)d_in[2];
    const float* ws1 = (const float*)d_in[3];
    const float* wn1 = (const float*)d_in[4];
    const float* b1  = (const float*)d_in[5];
    const float* ws2 = (const float*)d_in[6];
    const float* wn2 = (const float*)d_in[7];
    const float* b2  = (const float*)d_in[8];
    const float* ws3 = (const float*)d_in[9];
    const float* wn3 = (const float*)d_in[10];
    const float* b3  = (const float*)d_in[11];
    float* out = (float*)d_out;

    void *pA = nullptr, *pB = nullptr;
    cudaGetSymbolAddress(&pA, g_hA);
    cudaGetSymbolAddress(&pB, g_hB);
    float* hA = (float*)pA;
    float* hB = (float*)pB;

    const int EB = (N_EDGES + 255) / 256;
    const int NB = (N_NODES + 255) / 256;
    const int AGG_B = (N_NODES * 32 + 255) / 256;
    const int GEMM_B = (N_NODES + 127) / 128;

    // CSR build
    zero_cursor_k<<<NB, 256>>>();
    count_k<<<EB, 256>>>(dst);
    scan_k<<<1, 1024>>>();
    bucket_k<<<EB, 256>>>(src, dst);

    // Layer 1
    prepB_k<<<(128 * 256 + 255) / 256, 256>>>(ws1, wn1, 128, 128);
    agg_k<<<AGG_B, 256>>>(x);
    gemm_mma<128, 128, true><<<GEMM_B, 256>>>(x, b1, hA);

    // Layer 2
    prepB_k<<<(128 * 256 + 255) / 256, 256>>>(ws2, wn2, 128, 128);
    agg_k<<<AGG_B, 256>>>(hA);
    gemm_mma<128, 128, true><<<GEMM_B, 256>>>(hA, b2, hB);

    // Layer 3
    prepB_k<<<(64 * 256 + 255) / 256, 256>>>(ws3, wn3, N_OUT, 64);
    agg_k<<<AGG_B, 256>>>(hB);
    gemm_mma<64, N_OUT, false><<<GEMM_B, 256>>>(hB, b3, out);
}